// round 3
// baseline (speedup 1.0000x reference)
#include <cuda_runtime.h>

// Heirachical_Loss — closed-form collapse of the hierarchy matmul.
//
// loss = B - sum_i [ 0.5*S_all_i + 0.25*S100_i(t) + 0.125*S10_i(t) + 0.125*outputs[i,t] ]
// where S_all = row sum, S100 = sum of the 100-block containing t,
// S10 = sum of the 10-block containing t.

#define HL_C 1000
#define ROWS_PER_BLOCK 8
#define HL_THREADS 256
#define MAX_BLOCKS 8192

__device__ float g_hl_partials[MAX_BLOCKS];

__global__ void __launch_bounds__(HL_THREADS) hloss_main(
    const float* __restrict__ outputs,
    const int*   __restrict__ target,
    int B)
{
    const int warp = threadIdx.x >> 5;
    const int lane = threadIdx.x & 31;
    const int row  = blockIdx.x * ROWS_PER_BLOCK + warp;

    float win = 0.0f;
    if (row < B) {
        const int t = target[row];
        const float4* __restrict__ p =
            (const float4*)(outputs + (size_t)row * HL_C);

        // ---- Phase 1: full-row sum (250 float4 per row, front-batched loads) ----
        float4 v[7];
#pragma unroll
        for (int it = 0; it < 7; ++it)
            v[it] = p[it * 32 + lane];            // covers float4 idx 0..223
        float4 vt = make_float4(0.f, 0.f, 0.f, 0.f);
        if (lane < 26)
            vt = p[224 + lane];                   // covers idx 224..249

        float s = (vt.x + vt.y) + (vt.z + vt.w);
#pragma unroll
        for (int it = 0; it < 7; ++it)
            s += (v[it].x + v[it].y) + (v[it].z + v[it].w);

        // ---- Phase 2: special 100-block (L1 hit — just loaded) ----
        const int lo100 = (t / 100) * 100;        // 4-aligned
        const int lo10  = (t / 10)  * 10;
        float s100 = 0.f, s10 = 0.f, ot = 0.f;
        if (lane < 25) {
            float4 q = p[(lo100 >> 2) + lane];
            const int e0 = lo100 + lane * 4;
            float vals[4] = { q.x, q.y, q.z, q.w };
#pragma unroll
            for (int m = 0; m < 4; ++m) {
                const int e = e0 + m;
                const float vv = vals[m];
                s100 += vv;
                if ((unsigned)(e - lo10) < 10u) s10 += vv;
                if (e == t)                     ot  = vv;
            }
        }

        float part = 0.5f * s + 0.25f * s100 + 0.125f * s10 + 0.125f * ot;
#pragma unroll
        for (int off = 16; off; off >>= 1)
            part += __shfl_xor_sync(0xffffffffu, part, off);
        win = part;
    }

    // ---- Block reduce: one win per warp -> per-block partial of (1 - win) ----
    __shared__ float ws[ROWS_PER_BLOCK];
    if (lane == 0)
        ws[warp] = (row < B) ? (1.0f - win) : 0.0f;
    __syncthreads();
    if (threadIdx.x == 0) {
        float acc = 0.f;
#pragma unroll
        for (int w = 0; w < ROWS_PER_BLOCK; ++w) acc += ws[w];
        g_hl_partials[blockIdx.x] = acc;
    }
}

__global__ void __launch_bounds__(256) hloss_reduce(float* __restrict__ out, int n)
{
    __shared__ float sm[256];
    float acc = 0.f;
    for (int i = threadIdx.x; i < n; i += 256)
        acc += g_hl_partials[i];
    sm[threadIdx.x] = acc;
    __syncthreads();
#pragma unroll
    for (int s = 128; s; s >>= 1) {
        if (threadIdx.x < s) sm[threadIdx.x] += sm[threadIdx.x + s];
        __syncthreads();
    }
    if (threadIdx.x == 0) out[0] = sm[0];
}

extern "C" void kernel_launch(void* const* d_in, const int* in_sizes, int n_in,
                              void* d_out, int out_size)
{
    // metadata order: outputs [B*1000] float32, target [B] int32.
    // Defensive: pick the larger buffer as outputs.
    int i_o = 0, i_t = 1;
    if (n_in >= 2 && in_sizes[1] > in_sizes[0]) { i_o = 1; i_t = 0; }

    const float* outputs = (const float*)d_in[i_o];
    const int*   target  = (const int*)d_in[i_t];
    const int B = in_sizes[i_t];

    int nblocks = (B + ROWS_PER_BLOCK - 1) / ROWS_PER_BLOCK;
    if (nblocks > MAX_BLOCKS) nblocks = MAX_BLOCKS;   // B<=65536 expected (B=32768)

    hloss_main<<<nblocks, HL_THREADS>>>(outputs, target, B);
    hloss_reduce<<<1, 256>>>((float*)d_out, nblocks);
}

// round 4
// speedup vs baseline: 1.0412x; 1.0412x over previous
#include <cuda_runtime.h>

// Heirachical_Loss — closed-form collapse of the hierarchy matmul.
//
// loss = B - sum_i [ 0.5*S_all + 0.25*S100(t) + 0.125*S10(t) + 0.125*outputs[i,t] ]
// Fully fused: per-block partials + deterministic last-block final reduce
// (fixed summation order, no float atomics; counter auto-wraps for graph replay).

#define HL_C            1000
#define WARPS_PER_BLOCK 8
#define ROWS_PER_WARP   4
#define HL_THREADS      256
#define MAX_BLOCKS      4096   // supports B up to 131072 rows

__device__ float        g_hl_partials[MAX_BLOCKS];
__device__ unsigned int g_hl_count = 0;

__global__ void __launch_bounds__(HL_THREADS) hloss_fused(
    const float* __restrict__ outputs,
    const int*   __restrict__ target,
    float*       __restrict__ out,
    int B)
{
    const int warp = threadIdx.x >> 5;
    const int lane = threadIdx.x & 31;
    const int row0 = (blockIdx.x * WARPS_PER_BLOCK + warp) * ROWS_PER_WARP;

    float acc = 0.0f;   // sum of (1 - win) over this warp's rows (identical on all lanes)

#pragma unroll
    for (int r = 0; r < ROWS_PER_WARP; ++r) {
        const int row = row0 + r;
        if (row >= B) break;

        const int t = target[row];
        const float4* __restrict__ p =
            (const float4*)(outputs + (size_t)row * HL_C);

        const int lo100 = (t / 100) * 100;   // 4-aligned (100 % 4 == 0)
        const int lo10  = (t / 10)  * 10;

        // ---- Front-batch all loads for this row (max MLP) ----
        float4 v[7];
#pragma unroll
        for (int it = 0; it < 7; ++it)
            v[it] = p[it * 32 + lane];                    // float4 idx 0..223
        float4 vt = make_float4(0.f, 0.f, 0.f, 0.f);
        if (lane < 26) vt = p[224 + lane];                // idx 224..249
        float4 q  = make_float4(0.f, 0.f, 0.f, 0.f);
        if (lane < 25) q = p[(lo100 >> 2) + lane];        // target's 100-block (sector reuse)

        // ---- Full-row sum ----
        float s = (vt.x + vt.y) + (vt.z + vt.w);
#pragma unroll
        for (int it = 0; it < 7; ++it)
            s += (v[it].x + v[it].y) + (v[it].z + v[it].w);

        // ---- 100-block / 10-block / target-element terms ----
        float s100 = (q.x + q.y) + (q.z + q.w);           // q==0 for lane>=25
        float s10 = 0.f, ot = 0.f;
        {
            const int e0 = lo100 + lane * 4;
            const float vals[4] = { q.x, q.y, q.z, q.w };
#pragma unroll
            for (int m = 0; m < 4; ++m) {
                const int e = e0 + m;
                if ((unsigned)(e - lo10) < 10u) s10 += vals[m];
                if (e == t)                     ot   = vals[m];
            }
        }

        float part = 0.5f * s + 0.25f * s100 + 0.125f * s10 + 0.125f * ot;
#pragma unroll
        for (int off = 16; off; off >>= 1)
            part += __shfl_xor_sync(0xffffffffu, part, off);
        acc += 1.0f - part;                               // same value on every lane
    }

    // ---- Block reduce (one value per warp), write one partial per block ----
    __shared__ float ws[WARPS_PER_BLOCK];
    __shared__ bool  s_is_last;
    if (lane == 0) ws[warp] = acc;
    __syncthreads();
    if (threadIdx.x == 0) {
        float bsum = 0.f;
#pragma unroll
        for (int w = 0; w < WARPS_PER_BLOCK; ++w) bsum += ws[w];
        g_hl_partials[blockIdx.x] = bsum;
        __threadfence();
        // atomicInc wraps to 0 when old == gridDim.x-1 -> auto-reset per graph replay.
        unsigned v = atomicInc(&g_hl_count, gridDim.x - 1u);
        s_is_last = (v == gridDim.x - 1u);
    }
    __syncthreads();

    // ---- Last block: deterministic fixed-order final sum ----
    if (s_is_last) {
        __threadfence();
        float a = 0.f;
        for (int i = threadIdx.x; i < (int)gridDim.x; i += HL_THREADS)
            a += g_hl_partials[i];
        __shared__ float sm[HL_THREADS];
        sm[threadIdx.x] = a;
        __syncthreads();
#pragma unroll
        for (int s2 = HL_THREADS / 2; s2; s2 >>= 1) {
            if (threadIdx.x < s2) sm[threadIdx.x] += sm[threadIdx.x + s2];
            __syncthreads();
        }
        if (threadIdx.x == 0) out[0] = sm[0];
    }
}

extern "C" void kernel_launch(void* const* d_in, const int* in_sizes, int n_in,
                              void* d_out, int out_size)
{
    // metadata order: outputs [B*1000] float32, target [B] int32.
    int i_o = 0, i_t = 1;
    if (n_in >= 2 && in_sizes[1] > in_sizes[0]) { i_o = 1; i_t = 0; }

    const float* outputs = (const float*)d_in[i_o];
    const int*   target  = (const int*)d_in[i_t];
    const int B = in_sizes[i_t];

    const int rows_per_block = WARPS_PER_BLOCK * ROWS_PER_WARP;  // 32
    int nblocks = (B + rows_per_block - 1) / rows_per_block;     // 1024 for B=32768
    if (nblocks > MAX_BLOCKS) nblocks = MAX_BLOCKS;

    hloss_fused<<<nblocks, HL_THREADS>>>(outputs, target, (float*)d_out, B);
}